// round 2
// baseline (speedup 1.0000x reference)
#include <cuda_runtime.h>
#include <cuda_bf16.h>

// ---------------------------------------------------------------------------
// Fused ConditionedRecurrentEdgeModel
//   per edge:  w = relu(LN(winding @ Ww^T + bw))
//              x = [src,dest,edge_attr,u[batch],w]           (384)
//              x1 = relu(LN(x @ W1^T + b1))                  (128)
//              GRU(x1, h) -> h_new                           (128)
//              x_out = h_new @ Wx^T + bx                     (64)
// Strategy: 1 CTA = 64 edges, fp32 with packed fma.rn.f32x2, all stages fused,
// u-contribution to GEMM1 precomputed (batch has only 64 distinct values).
// ---------------------------------------------------------------------------

#define N_INC 64
#define E_INC 64
#define H2    128
#define H1    128
#define E_OUT 64
#define LN_EPS 1e-5f

#define BM 64            // edges per CTA
#define NT 256           // threads per CTA
#define XS_STR 324       // x tile stride (320 used cols + pad)
#define LSTR   132       // stride for 128-wide smem tiles
#define BSK    32        // K chunk

// smem layout (in floats)
#define X_S_OFF   0
#define X1_OFF    (BM * XS_STR)              // 20736
#define H_OFF     (X1_OFF + BM * LSTR)       // 29184
#define BS_OFF    (H_OFF + BM * LSTR)        // 37632  (2 * 32 * 132 = 8448)
#define WIN_OFF   (BS_OFF + 2 * BSK * LSTR)  // 46080  (128 floats)
#define BT_OFF    (WIN_OFF + 128)            // 46208  (64 ints)
#define SMEM_FLOATS (BT_OFF + 64)            // 46272
#define SMEM_BYTES  (SMEM_FLOATS * 4)        // 185088

__device__ float U1g[64 * 128];   // u @ W1_u^T  (per-batch precomputed)

// ---------------- packed f32x2 helpers ----------------
__device__ __forceinline__ void ffma2(unsigned long long &acc,
                                      unsigned long long a,
                                      unsigned long long b) {
    asm("fma.rn.f32x2 %0, %1, %2, %0;" : "+l"(acc) : "l"(a), "l"(b));
}
__device__ __forceinline__ unsigned long long bc2(float x) {
    unsigned long long r;
    asm("mov.b64 %0, {%1, %1};" : "=l"(r) : "f"(x));
    return r;
}
__device__ __forceinline__ float2 upk(unsigned long long v) {
    float2 f;
    asm("mov.b64 {%0, %1}, %2;" : "=f"(f.x), "=f"(f.y) : "l"(v));
    return f;
}
__device__ __forceinline__ float red16(float v) {
    v += __shfl_xor_sync(0xffffffffu, v, 8);
    v += __shfl_xor_sync(0xffffffffu, v, 4);
    v += __shfl_xor_sync(0xffffffffu, v, 2);
    v += __shfl_xor_sync(0xffffffffu, v, 1);
    return v;
}
__device__ __forceinline__ float sigf(float x) { return 1.f / (1.f + expf(-x)); }

// ---------------- weight staging: buf[kk][n] = Bg[n*ldg + kcol + kk] -------
template<int N>
__device__ __forceinline__ void stageB(float* buf, const float* __restrict__ Bg,
                                       int ldg, int kcol, int tid) {
    #pragma unroll
    for (int p = 0; p < N / 8; p++) {
        int idx = p * NT + tid;
        int kk = idx & 31;
        int n  = idx >> 5;
        buf[kk * LSTR + n] = Bg[n * ldg + kcol + kk];
    }
}

// ---------------- double-buffered GEMM over K (multiple of 32) -------------
// acc[i][p]: rows mg*4+i, col pair n0+2p. A is smem (stride LDA), B is gmem.
template<int LDA, int NPAIR>
__device__ __forceinline__ void gemm_loop(unsigned long long (&acc)[4][NPAIR],
                                          const float* As0,
                                          const float* __restrict__ Bg, int ldg,
                                          int K, float* Bs, int tid, int n0) {
    constexpr int NCOLS = NPAIR * 32;     // 128 or 64
    const int NC = K >> 5;
    stageB<NCOLS>(Bs, Bg, ldg, 0, tid);
    __syncthreads();
    for (int c = 0; c < NC; ++c) {
        if (c + 1 < NC)
            stageB<NCOLS>(Bs + ((c + 1) & 1) * (BSK * LSTR), Bg, ldg, (c + 1) * 32, tid);
        const float* B = Bs + (c & 1) * (BSK * LSTR) + n0;
        const float* A = As0 + c * 32;
        #pragma unroll 8
        for (int kk = 0; kk < 32; ++kk) {
            unsigned long long bp[NPAIR];
            #pragma unroll
            for (int p = 0; p < NPAIR / 2; p++) {
                ulonglong2 t = *reinterpret_cast<const ulonglong2*>(B + kk * LSTR + p * 4);
                bp[2 * p] = t.x;
                bp[2 * p + 1] = t.y;
            }
            #pragma unroll
            for (int i = 0; i < 4; i++) {
                unsigned long long a2 = bc2(A[i * LDA + kk]);
                #pragma unroll
                for (int p = 0; p < NPAIR; p++) ffma2(acc[i][p], a2, bp[p]);
            }
        }
        __syncthreads();
    }
}

// ---------------- U1 precompute: U1[b][n] = sum_k u[b][k] * W1[n][192+k] ----
__global__ void u1_kernel(const float* __restrict__ u, const float* __restrict__ W1) {
    int b = blockIdx.x;
    int n = threadIdx.x;
    float s = 0.f;
    #pragma unroll 8
    for (int k = 0; k < 64; k++)
        s += u[b * 64 + k] * W1[n * 384 + 192 + k];
    U1g[b * 128 + n] = s;
}

// ---------------- main fused kernel ----------------------------------------
__global__ __launch_bounds__(NT, 1)
void fused_kernel(const float* __restrict__ src, const float* __restrict__ dst,
                  const float* __restrict__ ea,  const float* __restrict__ hin,
                  const int*   __restrict__ batch, const float* __restrict__ winding,
                  const float* __restrict__ Ww,  const float* __restrict__ bw,
                  const float* __restrict__ gw,  const float* __restrict__ betaw,
                  const float* __restrict__ W1,  const float* __restrict__ b1,
                  const float* __restrict__ g1,  const float* __restrict__ beta1,
                  const float* __restrict__ Wih, const float* __restrict__ Whh,
                  const float* __restrict__ bih, const float* __restrict__ bhh,
                  const float* __restrict__ Wx,  const float* __restrict__ bx,
                  float* __restrict__ out_x, float* __restrict__ out_h, int E) {
    extern __shared__ float smem[];
    float* x_s  = smem + X_S_OFF;
    float* x1_s = smem + X1_OFF;     // also reused as hn_s
    float* h_s  = smem + H_OFF;
    float* Bs   = smem + BS_OFF;
    float* win_s = smem + WIN_OFF;
    int*   bt_s  = (int*)(smem + BT_OFF);
    float* r_s  = x_s;               // reuse of x tile after GEMM1
    float* z_s  = x_s + BM * LSTR;
    float* hn_s = x1_s;

    const int tid = threadIdx.x;
    const int mg  = tid >> 4;        // 0..15  (4 rows each)
    const int tn  = tid & 15;        // 0..15
    const int n0  = tn * 8;
    const int m0  = blockIdx.x * BM;

    // ---------------- Phase A: stage inputs ----------------
    if (tid < 64) {
        int r = tid;
        bt_s[r] = (m0 + r < E) ? batch[m0 + r] : 0;
    }
    if (tid < 128) {
        int r = tid >> 1, c = tid & 1;
        win_s[tid] = (m0 + r < E) ? winding[(m0 + r) * 2 + c] : 0.f;
    }
    {
        const float4 z4 = make_float4(0.f, 0.f, 0.f, 0.f);
        #pragma unroll
        for (int t = 0; t < 3; t++) {
            const float* g = (t == 0) ? src : (t == 1) ? dst : ea;
            int base = t * 64;
            #pragma unroll
            for (int p = 0; p < 4; p++) {
                int idx = p * NT + tid;
                int r = idx >> 4, c4 = idx & 15;
                float4 v = (m0 + r < E)
                    ? *reinterpret_cast<const float4*>(g + (size_t)(m0 + r) * 64 + c4 * 4) : z4;
                *reinterpret_cast<float4*>(x_s + r * XS_STR + base + c4 * 4) = v;
            }
        }
        #pragma unroll
        for (int p = 0; p < 8; p++) {
            int idx = p * NT + tid;
            int r = idx >> 5, c4 = idx & 31;
            float4 v = (m0 + r < E)
                ? *reinterpret_cast<const float4*>(hin + (size_t)(m0 + r) * 128 + c4 * 4) : z4;
            *reinterpret_cast<float4*>(h_s + r * LSTR + c4 * 4) = v;
        }
    }
    __syncthreads();

    // ---------------- Phase B: winding MLP -> x_s cols [192,320) ----------
    {
        float ww0[8], ww1[8], bwv[8], gwv[8], bev[8];
        #pragma unroll
        for (int j = 0; j < 8; j++) {
            int n = n0 + j;
            ww0[j] = Ww[n * 2 + 0];
            ww1[j] = Ww[n * 2 + 1];
            bwv[j] = bw[n]; gwv[j] = gw[n]; bev[j] = betaw[n];
        }
        #pragma unroll
        for (int i = 0; i < 4; i++) {
            int m = mg * 4 + i;
            float wa = win_s[2 * m], wb = win_s[2 * m + 1];
            float v[8], s = 0.f, q = 0.f;
            #pragma unroll
            for (int j = 0; j < 8; j++) {
                v[j] = fmaf(wa, ww0[j], fmaf(wb, ww1[j], bwv[j]));
                s += v[j]; q += v[j] * v[j];
            }
            s = red16(s); q = red16(q);
            float mu = s * (1.f / 128.f);
            float var = q * (1.f / 128.f) - mu * mu;
            float inv = rsqrtf(var + LN_EPS);
            #pragma unroll
            for (int j = 0; j < 8; j++) {
                float o = fmaf((v[j] - mu) * inv, gwv[j], bev[j]);
                x_s[m * XS_STR + 192 + n0 + j] = fmaxf(o, 0.f);
            }
        }
    }
    __syncthreads();

    // ---------------- GEMM1: x(320) @ W1^T  (+U1[batch]) -> LN -> relu -----
    {
        unsigned long long acc[4][4] = {};
        const float* Arow = x_s + mg * 4 * XS_STR;
        gemm_loop<XS_STR, 4>(acc, Arow,        W1,       384, 192, Bs, tid, n0);
        gemm_loop<XS_STR, 4>(acc, Arow + 192,  W1 + 256, 384, 128, Bs, tid, n0);

        float b1v[8], g1v[8], be1[8];
        #pragma unroll
        for (int j = 0; j < 8; j++) {
            int n = n0 + j;
            b1v[j] = b1[n]; g1v[j] = g1[n]; be1[j] = beta1[n];
        }
        #pragma unroll
        for (int i = 0; i < 4; i++) {
            int m = mg * 4 + i;
            const float* u1r = U1g + bt_s[m] * 128 + n0;
            float v[8], s = 0.f, q = 0.f;
            #pragma unroll
            for (int p = 0; p < 4; p++) {
                float2 f = upk(acc[i][p]);
                v[2 * p]     = f.x + b1v[2 * p]     + u1r[2 * p];
                v[2 * p + 1] = f.y + b1v[2 * p + 1] + u1r[2 * p + 1];
            }
            #pragma unroll
            for (int j = 0; j < 8; j++) { s += v[j]; q += v[j] * v[j]; }
            s = red16(s); q = red16(q);
            float mu = s * (1.f / 128.f);
            float var = q * (1.f / 128.f) - mu * mu;
            float inv = rsqrtf(var + LN_EPS);
            #pragma unroll
            for (int j = 0; j < 8; j++) {
                float o = fmaf((v[j] - mu) * inv, g1v[j], be1[j]);
                x1_s[m * LSTR + n0 + j] = fmaxf(o, 0.f);
            }
        }
    }
    __syncthreads();

    // ---------------- GRU: gates r, z, n -----------------------------------
    const float* x1row = x1_s + mg * 4 * LSTR;
    const float* hrow  = h_s  + mg * 4 * LSTR;
    for (int g = 0; g < 3; g++) {
        unsigned long long ai[4][4] = {};
        unsigned long long ah[4][4] = {};
        gemm_loop<LSTR, 4>(ai, x1row, Wih + g * 128 * 128, 128, 128, Bs, tid, n0);
        gemm_loop<LSTR, 4>(ah, hrow,  Whh + g * 128 * 128, 128, 128, Bs, tid, n0);

        float biv[8], bhv[8];
        #pragma unroll
        for (int j = 0; j < 8; j++) {
            biv[j] = bih[g * 128 + n0 + j];
            bhv[j] = bhh[g * 128 + n0 + j];
        }
        #pragma unroll
        for (int i = 0; i < 4; i++) {
            int m = mg * 4 + i;
            #pragma unroll
            for (int p = 0; p < 4; p++) {
                float2 fi = upk(ai[i][p]);
                float2 fh = upk(ah[i][p]);
                #pragma unroll
                for (int e = 0; e < 2; e++) {
                    int j = 2 * p + e;
                    float vi = (e ? fi.y : fi.x) + biv[j];
                    float vh = (e ? fh.y : fh.x) + bhv[j];
                    int a = m * LSTR + n0 + j;
                    if (g == 0) {
                        r_s[a] = sigf(vi + vh);
                    } else if (g == 1) {
                        z_s[a] = sigf(vi + vh);
                    } else {
                        float r  = r_s[a];
                        float zz = z_s[a];
                        float nn = tanhf(fmaf(r, vh, vi));
                        float hp = h_s[a];
                        hn_s[a] = fmaf(zz, hp - nn, nn);   // (1-z)*n + z*h
                    }
                }
            }
        }
    }
    __syncthreads();

    // ---------------- h_new -> gmem (coalesced) -----------------------------
    #pragma unroll
    for (int p = 0; p < 8; p++) {
        int idx = p * NT + tid;
        int r = idx >> 5, c4 = idx & 31;
        if (m0 + r < E) {
            float4 v = *reinterpret_cast<const float4*>(hn_s + r * LSTR + c4 * 4);
            *reinterpret_cast<float4*>(out_h + (size_t)(m0 + r) * 128 + c4 * 4) = v;
        }
    }

    // ---------------- x_out = h_new @ Wx^T + bx -----------------------------
    {
        unsigned long long aw[4][2] = {};
        const int n0w = tn * 4;
        gemm_loop<LSTR, 2>(aw, hn_s + mg * 4 * LSTR, Wx, 128, 128, Bs, tid, n0w);
        float bxv[4];
        #pragma unroll
        for (int j = 0; j < 4; j++) bxv[j] = bx[n0w + j];
        #pragma unroll
        for (int i = 0; i < 4; i++) {
            int m = mg * 4 + i;
            if (m0 + m < E) {
                float2 a = upk(aw[i][0]);
                float2 b = upk(aw[i][1]);
                float4 o = make_float4(a.x + bxv[0], a.y + bxv[1],
                                       b.x + bxv[2], b.y + bxv[3]);
                *reinterpret_cast<float4*>(out_x + (size_t)(m0 + m) * 64 + n0w) = o;
            }
        }
    }
}

// ---------------------------------------------------------------------------
extern "C" void kernel_launch(void* const* d_in, const int* in_sizes, int n_in,
                              void* d_out, int out_size) {
    const float* src     = (const float*)d_in[0];
    const float* dst     = (const float*)d_in[1];
    const float* ea      = (const float*)d_in[2];
    const float* hin     = (const float*)d_in[3];
    const float* u       = (const float*)d_in[4];
    const int*   batch   = (const int*)  d_in[5];
    const float* winding = (const float*)d_in[6];
    const float* Ww      = (const float*)d_in[7];
    const float* bw      = (const float*)d_in[8];
    const float* gw      = (const float*)d_in[9];
    const float* betaw   = (const float*)d_in[10];
    const float* W1      = (const float*)d_in[11];
    const float* b1      = (const float*)d_in[12];
    const float* g1      = (const float*)d_in[13];
    const float* beta1   = (const float*)d_in[14];
    const float* Wih     = (const float*)d_in[15];
    const float* Whh     = (const float*)d_in[16];
    const float* bih     = (const float*)d_in[17];
    const float* bhh     = (const float*)d_in[18];
    const float* Wx      = (const float*)d_in[19];
    const float* bx      = (const float*)d_in[20];

    int E = in_sizes[0] / 64;
    int B = in_sizes[4] / 64;

    float* out_x = (float*)d_out;                       // [E, 64]
    float* out_h = (float*)d_out + (size_t)E * 64;      // [E, 128]

    cudaFuncSetAttribute(fused_kernel,
                         cudaFuncAttributeMaxDynamicSharedMemorySize, SMEM_BYTES);

    u1_kernel<<<B, 128>>>(u, W1);
    int grid = (E + BM - 1) / BM;
    fused_kernel<<<grid, NT, SMEM_BYTES>>>(src, dst, ea, hin, batch, winding,
                                           Ww, bw, gw, betaw,
                                           W1, b1, g1, beta1,
                                           Wih, Whh, bih, bhh, Wx, bx,
                                           out_x, out_h, E);
}

// round 3
// speedup vs baseline: 1.0034x; 1.0034x over previous
#include <cuda_runtime.h>
#include <cuda_bf16.h>

// ---------------------------------------------------------------------------
// Fused ConditionedRecurrentEdgeModel
//   per edge:  w = relu(LN(winding @ Ww^T + bw))
//              x = [src,dest,edge_attr,u[batch],w]           (384)
//              x1 = relu(LN(x @ W1^T + b1))                  (128)
//              GRU(x1, h) -> h_new                           (128)
//              x_out = h_new @ Wx^T + bx                     (64)
// Strategy: 1 CTA = 64 edges, fp32 with packed fma.rn.f32x2, all stages fused,
// u-contribution to GEMM1 precomputed (batch has only 64 distinct values).
// ---------------------------------------------------------------------------

#define N_INC 64
#define E_INC 64
#define H2    128
#define H1    128
#define E_OUT 64
#define LN_EPS 1e-5f

#define BM 64            // edges per CTA
#define NT 256           // threads per CTA
#define XS_STR 324       // x tile stride (320 used cols + pad)
#define LSTR   132       // stride for 128-wide smem tiles
#define BSK    32        // K chunk

// smem layout (in floats)
#define X_S_OFF   0
#define X1_OFF    (BM * XS_STR)              // 20736
#define H_OFF     (X1_OFF + BM * LSTR)       // 29184
#define BS_OFF    (H_OFF + BM * LSTR)        // 37632  (2 * 32 * 132 = 8448)
#define WIN_OFF   (BS_OFF + 2 * BSK * LSTR)  // 46080  (128 floats)
#define BT_OFF    (WIN_OFF + 128)            // 46208  (64 ints)
#define SMEM_FLOATS (BT_OFF + 64)            // 46272
#define SMEM_BYTES  (SMEM_FLOATS * 4)        // 185088

__device__ float U1g[64 * 128];   // u @ W1_u^T  (per-batch precomputed)

// ---------------- packed f32x2 helpers ----------------
__device__ __forceinline__ void ffma2(unsigned long long &acc,
                                      unsigned long long a,
                                      unsigned long long b) {
    asm("fma.rn.f32x2 %0, %1, %2, %0;" : "+l"(acc) : "l"(a), "l"(b));
}
__device__ __forceinline__ unsigned long long bc2(float x) {
    unsigned long long r;
    asm("mov.b64 %0, {%1, %1};" : "=l"(r) : "f"(x));
    return r;
}
__device__ __forceinline__ float2 upk(unsigned long long v) {
    float2 f;
    asm("mov.b64 {%0, %1}, %2;" : "=f"(f.x), "=f"(f.y) : "l"(v));
    return f;
}
__device__ __forceinline__ float red16(float v) {
    v += __shfl_xor_sync(0xffffffffu, v, 8);
    v += __shfl_xor_sync(0xffffffffu, v, 4);
    v += __shfl_xor_sync(0xffffffffu, v, 2);
    v += __shfl_xor_sync(0xffffffffu, v, 1);
    return v;
}
__device__ __forceinline__ float sigf(float x) { return 1.f / (1.f + expf(-x)); }

// ---------------- weight staging: buf[kk][n] = Bg[n*ldg + kcol + kk] -------
template<int N>
__device__ __forceinline__ void stageB(float* buf, const float* __restrict__ Bg,
                                       int ldg, int kcol, int tid) {
    #pragma unroll
    for (int p = 0; p < N / 8; p++) {
        int idx = p * NT + tid;
        int kk = idx & 31;
        int n  = idx >> 5;
        buf[kk * LSTR + n] = Bg[n * ldg + kcol + kk];
    }
}

// ---------------- double-buffered GEMM over K (multiple of 32) -------------
// acc[i][p]: rows mg*4+i, col pair n0+2p. A is smem (stride LDA), B is gmem.
template<int LDA, int NPAIR>
__device__ __forceinline__ void gemm_loop(unsigned long long (&acc)[4][NPAIR],
                                          const float* As0,
                                          const float* __restrict__ Bg, int ldg,
                                          int K, float* Bs, int tid, int n0) {
    constexpr int NCOLS = NPAIR * 32;     // 128 or 64
    const int NC = K >> 5;
    stageB<NCOLS>(Bs, Bg, ldg, 0, tid);
    __syncthreads();
    for (int c = 0; c < NC; ++c) {
        if (c + 1 < NC)
            stageB<NCOLS>(Bs + ((c + 1) & 1) * (BSK * LSTR), Bg, ldg, (c + 1) * 32, tid);
        const float* B = Bs + (c & 1) * (BSK * LSTR) + n0;
        const float* A = As0 + c * 32;
        #pragma unroll 8
        for (int kk = 0; kk < 32; ++kk) {
            unsigned long long bp[NPAIR];
            #pragma unroll
            for (int p = 0; p < NPAIR / 2; p++) {
                ulonglong2 t = *reinterpret_cast<const ulonglong2*>(B + kk * LSTR + p * 4);
                bp[2 * p] = t.x;
                bp[2 * p + 1] = t.y;
            }
            #pragma unroll
            for (int i = 0; i < 4; i++) {
                unsigned long long a2 = bc2(A[i * LDA + kk]);
                #pragma unroll
                for (int p = 0; p < NPAIR; p++) ffma2(acc[i][p], a2, bp[p]);
            }
        }
        __syncthreads();
    }
}

// ---------------- U1 precompute: U1[b][n] = sum_k u[b][k] * W1[n][192+k] ----
__global__ void u1_kernel(const float* __restrict__ u, const float* __restrict__ W1) {
    int b = blockIdx.x;
    int n = threadIdx.x;
    float s = 0.f;
    #pragma unroll 8
    for (int k = 0; k < 64; k++)
        s += u[b * 64 + k] * W1[n * 384 + 192 + k];
    U1g[b * 128 + n] = s;
}

// ---------------- main fused kernel ----------------------------------------
__global__ __launch_bounds__(NT, 1)
void fused_kernel(const float* __restrict__ src, const float* __restrict__ dst,
                  const float* __restrict__ ea,  const float* __restrict__ hin,
                  const int*   __restrict__ batch, const float* __restrict__ winding,
                  const float* __restrict__ Ww,  const float* __restrict__ bw,
                  const float* __restrict__ gw,  const float* __restrict__ betaw,
                  const float* __restrict__ W1,  const float* __restrict__ b1,
                  const float* __restrict__ g1,  const float* __restrict__ beta1,
                  const float* __restrict__ Wih, const float* __restrict__ Whh,
                  const float* __restrict__ bih, const float* __restrict__ bhh,
                  const float* __restrict__ Wx,  const float* __restrict__ bx,
                  float* __restrict__ out_x, float* __restrict__ out_h, int E) {
    extern __shared__ float smem[];
    float* x_s  = smem + X_S_OFF;
    float* x1_s = smem + X1_OFF;     // also reused as hn_s
    float* h_s  = smem + H_OFF;
    float* Bs   = smem + BS_OFF;
    float* win_s = smem + WIN_OFF;
    int*   bt_s  = (int*)(smem + BT_OFF);
    float* r_s  = x_s;               // reuse of x tile after GEMM1
    float* z_s  = x_s + BM * LSTR;
    float* hn_s = x1_s;

    const int tid = threadIdx.x;
    const int mg  = tid >> 4;        // 0..15  (4 rows each)
    const int tn  = tid & 15;        // 0..15
    const int n0  = tn * 8;
    const int m0  = blockIdx.x * BM;

    // ---------------- Phase A: stage inputs ----------------
    if (tid < 64) {
        int r = tid;
        bt_s[r] = (m0 + r < E) ? batch[m0 + r] : 0;
    }
    if (tid < 128) {
        int r = tid >> 1, c = tid & 1;
        win_s[tid] = (m0 + r < E) ? winding[(m0 + r) * 2 + c] : 0.f;
    }
    {
        const float4 z4 = make_float4(0.f, 0.f, 0.f, 0.f);
        #pragma unroll
        for (int t = 0; t < 3; t++) {
            const float* g = (t == 0) ? src : (t == 1) ? dst : ea;
            int base = t * 64;
            #pragma unroll
            for (int p = 0; p < 4; p++) {
                int idx = p * NT + tid;
                int r = idx >> 4, c4 = idx & 15;
                float4 v = (m0 + r < E)
                    ? *reinterpret_cast<const float4*>(g + (size_t)(m0 + r) * 64 + c4 * 4) : z4;
                *reinterpret_cast<float4*>(x_s + r * XS_STR + base + c4 * 4) = v;
            }
        }
        #pragma unroll
        for (int p = 0; p < 8; p++) {
            int idx = p * NT + tid;
            int r = idx >> 5, c4 = idx & 31;
            float4 v = (m0 + r < E)
                ? *reinterpret_cast<const float4*>(hin + (size_t)(m0 + r) * 128 + c4 * 4) : z4;
            *reinterpret_cast<float4*>(h_s + r * LSTR + c4 * 4) = v;
        }
    }
    __syncthreads();

    // ---------------- Phase B: winding MLP -> x_s cols [192,320) ----------
    {
        float ww0[8], ww1[8], bwv[8], gwv[8], bev[8];
        #pragma unroll
        for (int j = 0; j < 8; j++) {
            int n = n0 + j;
            ww0[j] = Ww[n * 2 + 0];
            ww1[j] = Ww[n * 2 + 1];
            bwv[j] = bw[n]; gwv[j] = gw[n]; bev[j] = betaw[n];
        }
        #pragma unroll
        for (int i = 0; i < 4; i++) {
            int m = mg * 4 + i;
            float wa = win_s[2 * m], wb = win_s[2 * m + 1];
            float v[8], s = 0.f, q = 0.f;
            #pragma unroll
            for (int j = 0; j < 8; j++) {
                v[j] = fmaf(wa, ww0[j], fmaf(wb, ww1[j], bwv[j]));
                s += v[j]; q += v[j] * v[j];
            }
            s = red16(s); q = red16(q);
            float mu = s * (1.f / 128.f);
            float var = q * (1.f / 128.f) - mu * mu;
            float inv = rsqrtf(var + LN_EPS);
            #pragma unroll
            for (int j = 0; j < 8; j++) {
                float o = fmaf((v[j] - mu) * inv, gwv[j], bev[j]);
                x_s[m * XS_STR + 192 + n0 + j] = fmaxf(o, 0.f);
            }
        }
    }
    __syncthreads();

    // ---------------- GEMM1: x(320) @ W1^T  (+U1[batch]) -> LN -> relu -----
    {
        unsigned long long acc[4][4] = {};
        const float* Arow = x_s + mg * 4 * XS_STR;
        gemm_loop<XS_STR, 4>(acc, Arow,        W1,       384, 192, Bs, tid, n0);
        gemm_loop<XS_STR, 4>(acc, Arow + 192,  W1 + 256, 384, 128, Bs, tid, n0);

        float b1v[8], g1v[8], be1[8];
        #pragma unroll
        for (int j = 0; j < 8; j++) {
            int n = n0 + j;
            b1v[j] = b1[n]; g1v[j] = g1[n]; be1[j] = beta1[n];
        }
        #pragma unroll
        for (int i = 0; i < 4; i++) {
            int m = mg * 4 + i;
            const float* u1r = U1g + bt_s[m] * 128 + n0;
            float v[8], s = 0.f, q = 0.f;
            #pragma unroll
            for (int p = 0; p < 4; p++) {
                float2 f = upk(acc[i][p]);
                v[2 * p]     = f.x + b1v[2 * p]     + u1r[2 * p];
                v[2 * p + 1] = f.y + b1v[2 * p + 1] + u1r[2 * p + 1];
            }
            #pragma unroll
            for (int j = 0; j < 8; j++) { s += v[j]; q += v[j] * v[j]; }
            s = red16(s); q = red16(q);
            float mu = s * (1.f / 128.f);
            float var = q * (1.f / 128.f) - mu * mu;
            float inv = rsqrtf(var + LN_EPS);
            #pragma unroll
            for (int j = 0; j < 8; j++) {
                float o = fmaf((v[j] - mu) * inv, g1v[j], be1[j]);
                x1_s[m * LSTR + n0 + j] = fmaxf(o, 0.f);
            }
        }
    }
    __syncthreads();

    // ---------------- GRU: gates r, z, n -----------------------------------
    const float* x1row = x1_s + mg * 4 * LSTR;
    const float* hrow  = h_s  + mg * 4 * LSTR;
    for (int g = 0; g < 3; g++) {
        unsigned long long ai[4][4] = {};
        unsigned long long ah[4][4] = {};
        gemm_loop<LSTR, 4>(ai, x1row, Wih + g * 128 * 128, 128, 128, Bs, tid, n0);
        gemm_loop<LSTR, 4>(ah, hrow,  Whh + g * 128 * 128, 128, 128, Bs, tid, n0);

        float biv[8], bhv[8];
        #pragma unroll
        for (int j = 0; j < 8; j++) {
            biv[j] = bih[g * 128 + n0 + j];
            bhv[j] = bhh[g * 128 + n0 + j];
        }
        #pragma unroll
        for (int i = 0; i < 4; i++) {
            int m = mg * 4 + i;
            #pragma unroll
            for (int p = 0; p < 4; p++) {
                float2 fi = upk(ai[i][p]);
                float2 fh = upk(ah[i][p]);
                #pragma unroll
                for (int e = 0; e < 2; e++) {
                    int j = 2 * p + e;
                    float vi = (e ? fi.y : fi.x) + biv[j];
                    float vh = (e ? fh.y : fh.x) + bhv[j];
                    int a = m * LSTR + n0 + j;
                    if (g == 0) {
                        r_s[a] = sigf(vi + vh);
                    } else if (g == 1) {
                        z_s[a] = sigf(vi + vh);
                    } else {
                        float r  = r_s[a];
                        float zz = z_s[a];
                        float nn = tanhf(fmaf(r, vh, vi));
                        float hp = h_s[a];
                        hn_s[a] = fmaf(zz, hp - nn, nn);   // (1-z)*n + z*h
                    }
                }
            }
        }
    }
    __syncthreads();

    // ---------------- h_new -> gmem (coalesced) -----------------------------
    #pragma unroll
    for (int p = 0; p < 8; p++) {
        int idx = p * NT + tid;
        int r = idx >> 5, c4 = idx & 31;
        if (m0 + r < E) {
            float4 v = *reinterpret_cast<const float4*>(hn_s + r * LSTR + c4 * 4);
            *reinterpret_cast<float4*>(out_h + (size_t)(m0 + r) * 128 + c4 * 4) = v;
        }
    }

    // ---------------- x_out = h_new @ Wx^T + bx -----------------------------
    {
        unsigned long long aw[4][2] = {};
        const int n0w = tn * 4;
        gemm_loop<LSTR, 2>(aw, hn_s + mg * 4 * LSTR, Wx, 128, 128, Bs, tid, n0w);
        float bxv[4];
        #pragma unroll
        for (int j = 0; j < 4; j++) bxv[j] = bx[n0w + j];
        #pragma unroll
        for (int i = 0; i < 4; i++) {
            int m = mg * 4 + i;
            if (m0 + m < E) {
                float2 a = upk(aw[i][0]);
                float2 b = upk(aw[i][1]);
                float4 o = make_float4(a.x + bxv[0], a.y + bxv[1],
                                       b.x + bxv[2], b.y + bxv[3]);
                *reinterpret_cast<float4*>(out_x + (size_t)(m0 + m) * 64 + n0w) = o;
            }
        }
    }
}

// ---------------------------------------------------------------------------
extern "C" void kernel_launch(void* const* d_in, const int* in_sizes, int n_in,
                              void* d_out, int out_size) {
    const float* src     = (const float*)d_in[0];
    const float* dst     = (const float*)d_in[1];
    const float* ea      = (const float*)d_in[2];
    const float* hin     = (const float*)d_in[3];
    const float* u       = (const float*)d_in[4];
    const int*   batch   = (const int*)  d_in[5];
    const float* winding = (const float*)d_in[6];
    const float* Ww      = (const float*)d_in[7];
    const float* bw      = (const float*)d_in[8];
    const float* gw      = (const float*)d_in[9];
    const float* betaw   = (const float*)d_in[10];
    const float* W1      = (const float*)d_in[11];
    const float* b1      = (const float*)d_in[12];
    const float* g1      = (const float*)d_in[13];
    const float* beta1   = (const float*)d_in[14];
    const float* Wih     = (const float*)d_in[15];
    const float* Whh     = (const float*)d_in[16];
    const float* bih     = (const float*)d_in[17];
    const float* bhh     = (const float*)d_in[18];
    const float* Wx      = (const float*)d_in[19];
    const float* bx      = (const float*)d_in[20];

    int E = in_sizes[0] / 64;
    int B = in_sizes[4] / 64;

    float* out_x = (float*)d_out;                       // [E, 64]
    float* out_h = (float*)d_out + (size_t)E * 64;      // [E, 128]

    cudaFuncSetAttribute(fused_kernel,
                         cudaFuncAttributeMaxDynamicSharedMemorySize, SMEM_BYTES);

    u1_kernel<<<B, 128>>>(u, W1);
    int grid = (E + BM - 1) / BM;
    fused_kernel<<<grid, NT, SMEM_BYTES>>>(src, dst, ea, hin, batch, winding,
                                           Ww, bw, gw, betaw,
                                           W1, b1, g1, beta1,
                                           Wih, Whh, bih, bhh, Wx, bx,
                                           out_x, out_h, E);
}

// round 4
// speedup vs baseline: 2.9810x; 2.9708x over previous
#include <cuda_runtime.h>
#include <cuda_bf16.h>
#include <cstdint>

#define LN_EPS 1e-5f
#define BM 64
#define NTHR 256

// ---- dynamic smem byte offsets ----
#define AXH_OFF 0           // A(x) hi  : 64 x 328 bf16  (stride 656 B)
#define AXL_OFF 41984       // A(x) lo
#define ACH_OFF 83968       // A(cat x1|h) hi : 64 x 264 bf16 (stride 528 B)
#define ACL_OFF 117760      // A(cat) lo
#define BS_OFF  151552      // B staging: 2 bufs x (128*80*2) = 40960 B
#define PART_OFF 192512     // LN partials 64 x 4 x float2 = 2048 B
#define BT_OFF  194560      // batch idx, 64 ints
#define SMEM_BYTES 194816
#define AHH_OFF 0           // h_new hi (aliases dead Ax) stride 272 B
#define AHL_OFF 17408       // h_new lo
#define LDAX 656
#define LDAC 528
#define LDAH 272

__device__ float U1g[256 * 128];
__device__ __align__(16) __nv_bfloat16 W1h[40960],  W1l[40960];   // [128][320]
__device__ __align__(16) __nv_bfloat16 Wrh[32768],  Wrl[32768];   // [128][256]
__device__ __align__(16) __nv_bfloat16 Wzh[32768],  Wzl[32768];   // [128][256]
__device__ __align__(16) __nv_bfloat16 Wnih[16384], Wnil[16384];  // [128][128]
__device__ __align__(16) __nv_bfloat16 Wnhh[16384], Wnhl[16384];  // [128][128]
__device__ __align__(16) __nv_bfloat16 Wxh[8192],   Wxl[8192];    // [64][128]

// ---------------- helpers ----------------
__device__ __forceinline__ uint32_t sptr(const void* p) {
    return (uint32_t)__cvta_generic_to_shared(p);
}
__device__ __forceinline__ void mma_bf16(float (&d)[4], const uint32_t (&a)[4],
                                         uint32_t b0, uint32_t b1) {
    asm volatile(
        "mma.sync.aligned.m16n8k16.row.col.f32.bf16.bf16.f32 "
        "{%0,%1,%2,%3}, {%4,%5,%6,%7}, {%8,%9}, {%0,%1,%2,%3};\n"
        : "+f"(d[0]), "+f"(d[1]), "+f"(d[2]), "+f"(d[3])
        : "r"(a[0]), "r"(a[1]), "r"(a[2]), "r"(a[3]), "r"(b0), "r"(b1));
}
__device__ __forceinline__ void ldm4(uint32_t (&r)[4], uint32_t addr) {
    asm volatile("ldmatrix.sync.aligned.m8n8.x4.shared.b16 {%0,%1,%2,%3}, [%4];\n"
                 : "=r"(r[0]), "=r"(r[1]), "=r"(r[2]), "=r"(r[3]) : "r"(addr));
}
__device__ __forceinline__ void split2(float a, float b, uint32_t& H, uint32_t& L) {
    __nv_bfloat16 ha = __float2bfloat16(a), hb = __float2bfloat16(b);
    __nv_bfloat162 hp; hp.x = ha; hp.y = hb;
    __nv_bfloat162 lp;
    lp.x = __float2bfloat16(a - __bfloat162float(ha));
    lp.y = __float2bfloat16(b - __bfloat162float(hb));
    H = *reinterpret_cast<uint32_t*>(&hp);
    L = *reinterpret_cast<uint32_t*>(&lp);
}
__device__ __forceinline__ float sigf(float x) { return 1.f / (1.f + expf(-x)); }

// ---------------- B chunk load / store (NROWS rows, 32 k-cols, hi+lo) -------
template<int NROWS>
__device__ __forceinline__ void loadB(uint4* pre, const __nv_bfloat16* __restrict__ WH,
                                      const __nv_bfloat16* __restrict__ WL,
                                      int K, int kc, int tid) {
    constexpr int LPT = NROWS / 64;
    #pragma unroll
    for (int p = 0; p < LPT; p++) {
        int idx = p * NTHR + tid;
        int n = idx >> 2, s = idx & 3;
        pre[p]       = *reinterpret_cast<const uint4*>(WH + n * K + kc + s * 8);
        pre[LPT + p] = *reinterpret_cast<const uint4*>(WL + n * K + kc + s * 8);
    }
}
template<int NROWS>
__device__ __forceinline__ void storeB(char* buf, const uint4* pre, int tid) {
    constexpr int LPT = NROWS / 64;
    #pragma unroll
    for (int p = 0; p < LPT; p++) {
        int idx = p * NTHR + tid;
        int n = idx >> 2, s = idx & 3;
        *reinterpret_cast<uint4*>(buf + n * 80 + s * 16) = pre[p];
        *reinterpret_cast<uint4*>(buf + NROWS * 80 + n * 80 + s * 16) = pre[LPT + p];
    }
}

// ---------------- 3-split GEMM core -----------------------------------------
// acc[MT][NTL][4]: warp tile MT*16 rows x NTL*8 cols. A smem (hi/lo) row-major,
// W gmem [NROWS][K] hi/lo. K % 32 == 0.
template<int MT, int NTL, int NROWS>
__device__ __forceinline__ void run_gemm(float (&acc)[MT][NTL][4],
                                         uint32_t aH, uint32_t aL, int ldaB,
                                         const __nv_bfloat16* __restrict__ WH,
                                         const __nv_bfloat16* __restrict__ WL,
                                         int K, char* bsPtr, uint32_t bsAddr,
                                         int colBase, int tid) {
    constexpr int BUFSZ = NROWS * 160;
    constexpr int LPT = NROWS / 64;
    const int lane = tid & 31;
    uint32_t aoff = (lane % 16) * ldaB + (lane / 16) * 16;
    uint32_t aAH = aH + aoff, aAL = aL + aoff;
    int brow = (lane & 7) + ((lane & 16) ? 8 : 0);
    uint32_t boff = (uint32_t)(colBase + brow) * 80 + ((lane & 8) ? 16 : 0);
    const int NC = K >> 5;
    {   // prologue: stage chunk 0
        uint4 t[2 * LPT];
        loadB<NROWS>(t, WH, WL, K, 0, tid);
        storeB<NROWS>(bsPtr, t, tid);
    }
    __syncthreads();
    for (int c = 0; c < NC; ++c) {
        uint4 pre[2 * LPT];
        bool hasNext = (c + 1) < NC;
        if (hasNext) loadB<NROWS>(pre, WH, WL, K, (c + 1) * 32, tid);
        uint32_t bufH = bsAddr + (c & 1) * BUFSZ + boff;
        uint32_t aCH = aAH + c * 64, aCL = aAL + c * 64;
        #pragma unroll
        for (int ks = 0; ks < 2; ++ks) {
            uint32_t ah_[MT][4], al_[MT][4];
            #pragma unroll
            for (int mt = 0; mt < MT; mt++) {
                ldm4(ah_[mt], aCH + mt * 16 * ldaB + ks * 32);
                ldm4(al_[mt], aCL + mt * 16 * ldaB + ks * 32);
            }
            #pragma unroll
            for (int q = 0; q < NTL / 2; q++) {
                uint32_t bh[4], bl[4];
                ldm4(bh, bufH + q * 16 * 80 + ks * 32);
                ldm4(bl, bufH + NROWS * 80 + q * 16 * 80 + ks * 32);
                #pragma unroll
                for (int mt = 0; mt < MT; mt++) {
                    mma_bf16(acc[mt][2 * q],     ah_[mt], bh[0], bh[1]);
                    mma_bf16(acc[mt][2 * q],     ah_[mt], bl[0], bl[1]);
                    mma_bf16(acc[mt][2 * q],     al_[mt], bh[0], bh[1]);
                    mma_bf16(acc[mt][2 * q + 1], ah_[mt], bh[2], bh[3]);
                    mma_bf16(acc[mt][2 * q + 1], ah_[mt], bl[2], bl[3]);
                    mma_bf16(acc[mt][2 * q + 1], al_[mt], bh[2], bh[3]);
                }
            }
        }
        if (hasNext) storeB<NROWS>(bsPtr + ((c + 1) & 1) * BUFSZ, pre, tid);
        __syncthreads();
    }
}

// ---------------- weight prep (fp32 -> bf16 hi/lo, gathers baked) ------------
__global__ void prep_kernel(const float* __restrict__ W1, const float* __restrict__ Wih,
                            const float* __restrict__ Whh, const float* __restrict__ Wx) {
    int i = blockIdx.x * 256 + threadIdx.x;
    if (i >= 147456) return;
    float v; __nv_bfloat16 *H, *L; int o;
    if (i < 40960) {
        int n = i / 320, k = i % 320;
        v = W1[n * 384 + (k < 192 ? k : k + 64)];
        H = W1h; L = W1l; o = i;
    } else if (i < 73728) {
        int j = i - 40960, n = j / 256, k = j % 256;
        v = (k < 128) ? Wih[n * 128 + k] : Whh[n * 128 + k - 128];
        H = Wrh; L = Wrl; o = j;
    } else if (i < 106496) {
        int j = i - 73728, n = j / 256, k = j % 256;
        v = (k < 128) ? Wih[(128 + n) * 128 + k] : Whh[(128 + n) * 128 + k - 128];
        H = Wzh; L = Wzl; o = j;
    } else if (i < 122880) {
        int j = i - 106496; v = Wih[256 * 128 + j]; H = Wnih; L = Wnil; o = j;
    } else if (i < 139264) {
        int j = i - 122880; v = Whh[256 * 128 + j]; H = Wnhh; L = Wnhl; o = j;
    } else {
        int j = i - 139264; v = Wx[j]; H = Wxh; L = Wxl; o = j;
    }
    __nv_bfloat16 h = __float2bfloat16(v);
    H[o] = h;
    L[o] = __float2bfloat16(v - __bfloat162float(h));
}

__global__ void u1_kernel(const float* __restrict__ u, const float* __restrict__ W1) {
    int b = blockIdx.x, n = threadIdx.x;
    float s = 0.f;
    #pragma unroll 8
    for (int k = 0; k < 64; k++)
        s += u[b * 64 + k] * W1[n * 384 + 192 + k];
    U1g[b * 128 + n] = s;
}

// ---------------- main fused kernel ------------------------------------------
__global__ __launch_bounds__(NTHR, 1)
void fused_kernel(const float* __restrict__ src, const float* __restrict__ dst,
                  const float* __restrict__ ea,  const float* __restrict__ hin,
                  const int*   __restrict__ batch, const float* __restrict__ winding,
                  const float* __restrict__ Ww,  const float* __restrict__ bw,
                  const float* __restrict__ gw,  const float* __restrict__ betaw,
                  const float* __restrict__ b1,  const float* __restrict__ g1,
                  const float* __restrict__ beta1,
                  const float* __restrict__ bih, const float* __restrict__ bhh,
                  const float* __restrict__ bx,
                  float* __restrict__ out_x, float* __restrict__ out_h, int E) {
    extern __shared__ char sm[];
    const uint32_t SP = sptr(sm);
    const int tid = threadIdx.x;
    const int lane = tid & 31, w = tid >> 5;
    const int wm = w & 1, wn = w >> 1;            // 2 x 4 warp grid
    const int rowBase = wm * 32, colBase = wn * 32;
    const int qr = lane >> 2, qc = (lane & 3) * 2;
    const int m0 = blockIdx.x * BM;
    float2* PART = reinterpret_cast<float2*>(sm + PART_OFF);
    int* bt_s = reinterpret_cast<int*>(sm + BT_OFF);
    char* bsPtr = sm + BS_OFF;
    const uint32_t bsAddr = SP + BS_OFF;

    // ---- Phase A: stage inputs (split to bf16 hi/lo) ----
    if (tid < 64) bt_s[tid] = (m0 + tid < E) ? batch[m0 + tid] : 0;
    #pragma unroll
    for (int t = 0; t < 3; t++) {
        const float* g = (t == 0) ? src : (t == 1) ? dst : ea;
        #pragma unroll
        for (int p = 0; p < 4; p++) {
            int idx = p * NTHR + tid;
            int r = idx >> 4, c4 = (idx & 15) * 4;
            float4 v = (m0 + r < E)
                ? *reinterpret_cast<const float4*>(g + (size_t)(m0 + r) * 64 + c4)
                : make_float4(0.f, 0.f, 0.f, 0.f);
            uint32_t h0, l0, h1, l1;
            split2(v.x, v.y, h0, l0); split2(v.z, v.w, h1, l1);
            int off = r * LDAX + (t * 64 + c4) * 2;
            *reinterpret_cast<uint2*>(sm + AXH_OFF + off) = make_uint2(h0, h1);
            *reinterpret_cast<uint2*>(sm + AXL_OFF + off) = make_uint2(l0, l1);
        }
    }
    #pragma unroll
    for (int p = 0; p < 8; p++) {
        int idx = p * NTHR + tid;
        int r = idx >> 5, c4 = (idx & 31) * 4;
        float4 v = (m0 + r < E)
            ? *reinterpret_cast<const float4*>(hin + (size_t)(m0 + r) * 128 + c4)
            : make_float4(0.f, 0.f, 0.f, 0.f);
        uint32_t h0, l0, h1, l1;
        split2(v.x, v.y, h0, l0); split2(v.z, v.w, h1, l1);
        int off = r * LDAC + (128 + c4) * 2;
        *reinterpret_cast<uint2*>(sm + ACH_OFF + off) = make_uint2(h0, h1);
        *reinterpret_cast<uint2*>(sm + ACL_OFF + off) = make_uint2(l0, l1);
    }
    // ---- winding MLP -> x cols [192,320) ----
    {
        int m = tid >> 2, q = tid & 3;
        float wa = 0.f, wb = 0.f;
        if (m0 + m < E) { wa = winding[(m0 + m) * 2]; wb = winding[(m0 + m) * 2 + 1]; }
        float v[32]; float s = 0.f, sq = 0.f;
        #pragma unroll
        for (int j = 0; j < 32; j++) {
            int c = q * 32 + j;
            v[j] = fmaf(wa, Ww[c * 2], fmaf(wb, Ww[c * 2 + 1], bw[c]));
            s += v[j]; sq += v[j] * v[j];
        }
        s  += __shfl_xor_sync(0xffffffffu, s, 1);  s  += __shfl_xor_sync(0xffffffffu, s, 2);
        sq += __shfl_xor_sync(0xffffffffu, sq, 1); sq += __shfl_xor_sync(0xffffffffu, sq, 2);
        float mu = s * (1.f / 128.f);
        float inv = rsqrtf(sq * (1.f / 128.f) - mu * mu + LN_EPS);
        #pragma unroll
        for (int j = 0; j < 32; j += 2) {
            int c = q * 32 + j;
            float o0 = fmaxf(fmaf((v[j] - mu) * inv, gw[c], betaw[c]), 0.f);
            float o1 = fmaxf(fmaf((v[j + 1] - mu) * inv, gw[c + 1], betaw[c + 1]), 0.f);
            uint32_t H, L; split2(o0, o1, H, L);
            int off = m * LDAX + (192 + c) * 2;
            *reinterpret_cast<uint32_t*>(sm + AXH_OFF + off) = H;
            *reinterpret_cast<uint32_t*>(sm + AXL_OFF + off) = L;
        }
    }
    __syncthreads();

    // ---- GEMM1: x(320) @ W1^T -> +U1+b1 -> LN -> relu -> Acat[:,0:128] ----
    {
        float acc[2][4][4] = {};
        run_gemm<2, 4, 128>(acc, SP + AXH_OFF + rowBase * LDAX,
                            SP + AXL_OFF + rowBase * LDAX, LDAX,
                            W1h, W1l, 320, bsPtr, bsAddr, colBase, tid);
        float b1v[8], g1v[8], be1[8]; int c8[8];
        #pragma unroll
        for (int j = 0; j < 8; j++) {
            c8[j] = colBase + (j >> 1) * 8 + qc + (j & 1);
            b1v[j] = b1[c8[j]]; g1v[j] = g1[c8[j]]; be1[j] = beta1[c8[j]];
        }
        #pragma unroll
        for (int mt = 0; mt < 2; mt++)
            #pragma unroll
            for (int h = 0; h < 2; h++) {
                int row = rowBase + mt * 16 + qr + h * 8;
                const float* u1r = U1g + bt_s[row] * 128;
                float s = 0.f, sq = 0.f;
                #pragma unroll
                for (int j = 0; j < 8; j++) {
                    float vv = acc[mt][j >> 1][2 * h + (j & 1)] + b1v[j] + u1r[c8[j]];
                    acc[mt][j >> 1][2 * h + (j & 1)] = vv;
                    s += vv; sq += vv * vv;
                }
                s  += __shfl_xor_sync(0xffffffffu, s, 1);  s  += __shfl_xor_sync(0xffffffffu, s, 2);
                sq += __shfl_xor_sync(0xffffffffu, sq, 1); sq += __shfl_xor_sync(0xffffffffu, sq, 2);
                if ((lane & 3) == 0) PART[row * 4 + wn] = make_float2(s, sq);
            }
        __syncthreads();
        #pragma unroll
        for (int mt = 0; mt < 2; mt++)
            #pragma unroll
            for (int h = 0; h < 2; h++) {
                int row = rowBase + mt * 16 + qr + h * 8;
                float2 p0 = PART[row * 4], p1 = PART[row * 4 + 1],
                       p2 = PART[row * 4 + 2], p3 = PART[row * 4 + 3];
                float S = p0.x + p1.x + p2.x + p3.x;
                float Q = p0.y + p1.y + p2.y + p3.y;
                float mu = S * (1.f / 128.f);
                float inv = rsqrtf(Q * (1.f / 128.f) - mu * mu + LN_EPS);
                #pragma unroll
                for (int nt = 0; nt < 4; nt++) {
                    float o0 = fmaxf(fmaf((acc[mt][nt][2 * h] - mu) * inv,
                                          g1v[nt * 2], be1[nt * 2]), 0.f);
                    float o1 = fmaxf(fmaf((acc[mt][nt][2 * h + 1] - mu) * inv,
                                          g1v[nt * 2 + 1], be1[nt * 2 + 1]), 0.f);
                    uint32_t H, L; split2(o0, o1, H, L);
                    int off = row * LDAC + c8[nt * 2] * 2;
                    *reinterpret_cast<uint32_t*>(sm + ACH_OFF + off) = H;
                    *reinterpret_cast<uint32_t*>(sm + ACL_OFF + off) = L;
                }
            }
    }
    // NOTE: run_gemm prologue sync makes ACH/ACL writes visible before reads.

    // ---- GRU gates: in, hn, r -> fold n; then z -> h_new ----
    uint32_t aCH = SP + ACH_OFF + rowBase * LDAC;
    uint32_t aCL = SP + ACL_OFF + rowBase * LDAC;
    float nacc[2][4][4];
    int c8[8];
    #pragma unroll
    for (int j = 0; j < 8; j++) c8[j] = colBase + (j >> 1) * 8 + qc + (j & 1);
    {
        float accI[2][4][4] = {}, accH[2][4][4] = {}, accR[2][4][4] = {};
        run_gemm<2, 4, 128>(accI, aCH, aCL, LDAC, Wnih, Wnil, 128, bsPtr, bsAddr, colBase, tid);
        run_gemm<2, 4, 128>(accH, aCH + 256, aCL + 256, LDAC, Wnhh, Wnhl, 128, bsPtr, bsAddr, colBase, tid);
        run_gemm<2, 4, 128>(accR, aCH, aCL, LDAC, Wrh, Wrl, 256, bsPtr, bsAddr, colBase, tid);
        #pragma unroll
        for (int mt = 0; mt < 2; mt++)
            #pragma unroll
            for (int j = 0; j < 8; j++) {
                int nt = j >> 1, e = j & 1;
                float bi_r = bih[c8[j]] + bhh[c8[j]];
                float bi_n = bih[256 + c8[j]], bh_n = bhh[256 + c8[j]];
                #pragma unroll
                for (int h = 0; h < 2; h++) {
                    float r = sigf(accR[mt][nt][2 * h + e] + bi_r);
                    nacc[mt][nt][2 * h + e] =
                        tanhf(accI[mt][nt][2 * h + e] + bi_n +
                              r * (accH[mt][nt][2 * h + e] + bh_n));
                }
            }
    }
    {
        float accZ[2][4][4] = {};
        run_gemm<2, 4, 128>(accZ, aCH, aCL, LDAC, Wzh, Wzl, 256, bsPtr, bsAddr, colBase, tid);
        #pragma unroll
        for (int mt = 0; mt < 2; mt++)
            #pragma unroll
            for (int h = 0; h < 2; h++) {
                int row = rowBase + mt * 16 + qr + h * 8;
                #pragma unroll
                for (int nt = 0; nt < 4; nt++) {
                    int c0 = c8[nt * 2];
                    // reconstruct h from hi+lo planes
                    uint32_t Hh = *reinterpret_cast<uint32_t*>(sm + ACH_OFF + row * LDAC + (128 + c0) * 2);
                    uint32_t Hl = *reinterpret_cast<uint32_t*>(sm + ACL_OFF + row * LDAC + (128 + c0) * 2);
                    __nv_bfloat162 bh2 = *reinterpret_cast<__nv_bfloat162*>(&Hh);
                    __nv_bfloat162 bl2 = *reinterpret_cast<__nv_bfloat162*>(&Hl);
                    float hp0 = __bfloat162float(bh2.x) + __bfloat162float(bl2.x);
                    float hp1 = __bfloat162float(bh2.y) + __bfloat162float(bl2.y);
                    float z0 = sigf(accZ[mt][nt][2 * h] + bih[128 + c0] + bhh[128 + c0]);
                    float z1 = sigf(accZ[mt][nt][2 * h + 1] + bih[128 + c0 + 1] + bhh[128 + c0 + 1]);
                    float n0 = nacc[mt][nt][2 * h], n1 = nacc[mt][nt][2 * h + 1];
                    float hn0 = fmaf(z0, hp0 - n0, n0);
                    float hn1 = fmaf(z1, hp1 - n1, n1);
                    if (m0 + row < E)
                        *reinterpret_cast<float2*>(out_h + (size_t)(m0 + row) * 128 + c0) =
                            make_float2(hn0, hn1);
                    uint32_t H, L; split2(hn0, hn1, H, L);
                    *reinterpret_cast<uint32_t*>(sm + AHH_OFF + row * LDAH + c0 * 2) = H;
                    *reinterpret_cast<uint32_t*>(sm + AHL_OFF + row * LDAH + c0 * 2) = L;
                }
            }
    }
    // ---- x_out = h_new @ Wx^T + bx  (warps: 4 in M x 2 in N) ----
    {
        const int rb2 = (w & 3) * 16, cb2 = (w >> 2) * 32;
        float accX[1][4][4] = {};
        run_gemm<1, 4, 64>(accX, SP + AHH_OFF + rb2 * LDAH,
                           SP + AHL_OFF + rb2 * LDAH, LDAH,
                           Wxh, Wxl, 128, bsPtr, bsAddr, cb2, tid);
        #pragma unroll
        for (int h = 0; h < 2; h++) {
            int row = rb2 + qr + h * 8;
            if (m0 + row < E) {
                #pragma unroll
                for (int nt = 0; nt < 4; nt++) {
                    int c = cb2 + nt * 8 + qc;
                    *reinterpret_cast<float2*>(out_x + (size_t)(m0 + row) * 64 + c) =
                        make_float2(accX[0][nt][2 * h] + bx[c],
                                    accX[0][nt][2 * h + 1] + bx[c + 1]);
                }
            }
        }
    }
}

// ---------------------------------------------------------------------------
extern "C" void kernel_launch(void* const* d_in, const int* in_sizes, int n_in,
                              void* d_out, int out_size) {
    const float* src     = (const float*)d_in[0];
    const float* dst     = (const float*)d_in[1];
    const float* ea      = (const float*)d_in[2];
    const float* hin     = (const float*)d_in[3];
    const float* u       = (const float*)d_in[4];
    const int*   batch   = (const int*)  d_in[5];
    const float* winding = (const float*)d_in[6];
    const float* Ww      = (const float*)d_in[7];
    const float* bw      = (const float*)d_in[8];
    const float* gw      = (const float*)d_in[9];
    const float* betaw   = (const float*)d_in[10];
    const float* W1      = (const float*)d_in[11];
    const float* b1      = (const float*)d_in[12];
    const float* g1      = (const float*)d_in[13];
    const float* beta1   = (const float*)d_in[14];
    const float* Wih     = (const float*)d_in[15];
    const float* Whh     = (const float*)d_in[16];
    const float* bih     = (const float*)d_in[17];
    const float* bhh     = (const float*)d_in[18];
    const float* Wx      = (const float*)d_in[19];
    const float* bx      = (const float*)d_in[20];

    int E = in_sizes[0] / 64;
    int B = in_sizes[4] / 64;
    float* out_x = (float*)d_out;
    float* out_h = (float*)d_out + (size_t)E * 64;

    cudaFuncSetAttribute(fused_kernel,
                         cudaFuncAttributeMaxDynamicSharedMemorySize, SMEM_BYTES);
    prep_kernel<<<576, 256>>>(W1, Wih, Whh, Wx);
    u1_kernel<<<B, 128>>>(u, W1);
    int grid = (E + BM - 1) / BM;
    fused_kernel<<<grid, NTHR, SMEM_BYTES>>>(src, dst, ea, hin, batch, winding,
                                             Ww, bw, gw, betaw,
                                             b1, g1, beta1, bih, bhh, bx,
                                             out_x, out_h, E);
}

// round 7
// speedup vs baseline: 3.4393x; 1.1537x over previous
#include <cuda_runtime.h>
#include <cuda_bf16.h>
#include <cstdint>

#define LN_EPS 1e-5f
#define BM 128
#define NTHR 512

// ---- dynamic smem byte offsets ----
#define AXH_OFF 0            // A(x) hi : 128 x 328 bf16 (stride 656 B) = 83968
#define AXL_OFF 83968        // A(x) lo                              -> 167936
#define ACH_OFF 0            // cat(x1|h) hi : 128 x 264 bf16 (stride 528) aliases x
#define ACL_OFF 67584        //                                      -> 135168
#define BS_OFF  167936       // B staging: 2 bufs x (128*80*2) = 40960 -> 208896
#define PART_OFF 208896      // LN partials 128 x 4 x float2 = 4096  -> 212992
#define BT_OFF  212992       // batch idx, 128 ints = 512            -> 213504
#define SMEM_BYTES 213504
#define LDAX 656
#define LDAC 528

__device__ float U1g[256 * 128];
__device__ __align__(16) __nv_bfloat16 W1h[40960],  W1l[40960];   // [128][320]
__device__ __align__(16) __nv_bfloat16 Wrh[32768],  Wrl[32768];   // [128][256]
__device__ __align__(16) __nv_bfloat16 Wzh[32768],  Wzl[32768];   // [128][256]
__device__ __align__(16) __nv_bfloat16 Wnih[16384], Wnil[16384];  // [128][128]
__device__ __align__(16) __nv_bfloat16 Wnhh[16384], Wnhl[16384];  // [128][128]
__device__ __align__(16) __nv_bfloat16 Wxh[8192],   Wxl[8192];    // [64][128]

// ---------------- helpers ----------------
__device__ __forceinline__ uint32_t sptr(const void* p) {
    return (uint32_t)__cvta_generic_to_shared(p);
}
__device__ __forceinline__ void mma_bf16(float (&d)[4], const uint32_t (&a)[4],
                                         uint32_t b0, uint32_t b1) {
    asm volatile(
        "mma.sync.aligned.m16n8k16.row.col.f32.bf16.bf16.f32 "
        "{%0,%1,%2,%3}, {%4,%5,%6,%7}, {%8,%9}, {%0,%1,%2,%3};\n"
        : "+f"(d[0]), "+f"(d[1]), "+f"(d[2]), "+f"(d[3])
        : "r"(a[0]), "r"(a[1]), "r"(a[2]), "r"(a[3]), "r"(b0), "r"(b1));
}
__device__ __forceinline__ void ldm4(uint32_t (&r)[4], uint32_t addr) {
    asm volatile("ldmatrix.sync.aligned.m8n8.x4.shared.b16 {%0,%1,%2,%3}, [%4];\n"
                 : "=r"(r[0]), "=r"(r[1]), "=r"(r[2]), "=r"(r[3]) : "r"(addr));
}
__device__ __forceinline__ void split2(float a, float b, uint32_t& H, uint32_t& L) {
    __nv_bfloat16 ha = __float2bfloat16(a), hb = __float2bfloat16(b);
    __nv_bfloat162 hp; hp.x = ha; hp.y = hb;
    __nv_bfloat162 lp;
    lp.x = __float2bfloat16(a - __bfloat162float(ha));
    lp.y = __float2bfloat16(b - __bfloat162float(hb));
    H = *reinterpret_cast<uint32_t*>(&hp);
    L = *reinterpret_cast<uint32_t*>(&lp);
}
__device__ __forceinline__ float sigf(float x) { return 1.f / (1.f + __expf(-x)); }
__device__ __forceinline__ float tanhfast(float x) { return fmaf(2.f, sigf(2.f * x), -1.f); }

// ---------------- B chunk load / store (NROWS rows, 32 k-cols, hi+lo) -------
template<int NROWS>
__device__ __forceinline__ void loadB(uint4* pre, const __nv_bfloat16* __restrict__ WH,
                                      const __nv_bfloat16* __restrict__ WL,
                                      int K, int kc, int tid) {
    if (NROWS * 4 >= NTHR || tid < NROWS * 4) {
        int n = tid >> 2, s = tid & 3;
        pre[0] = *reinterpret_cast<const uint4*>(WH + n * K + kc + s * 8);
        pre[1] = *reinterpret_cast<const uint4*>(WL + n * K + kc + s * 8);
    }
}
template<int NROWS>
__device__ __forceinline__ void storeB(char* buf, const uint4* pre, int tid) {
    if (NROWS * 4 >= NTHR || tid < NROWS * 4) {
        int n = tid >> 2, s = tid & 3;
        *reinterpret_cast<uint4*>(buf + n * 80 + s * 16) = pre[0];
        *reinterpret_cast<uint4*>(buf + NROWS * 80 + n * 80 + s * 16) = pre[1];
    }
}

// ---------------- 3-split GEMM core -----------------------------------------
// acc[MT][NTL][4]: warp tile MT*16 rows x NTL*8 cols. A smem hi/lo row-major,
// W gmem [NROWS][K] hi/lo. K % 32 == 0.
template<int MT, int NTL, int NROWS>
__device__ __forceinline__ void run_gemm(float (&acc)[MT][NTL][4],
                                         uint32_t aH, uint32_t aL, int ldaB,
                                         const __nv_bfloat16* __restrict__ WH,
                                         const __nv_bfloat16* __restrict__ WL,
                                         int K, char* bsPtr, uint32_t bsAddr,
                                         int colBase, int tid) {
    constexpr int BUFSZ = NROWS * 160;
    const int lane = tid & 31;
    uint32_t aoff = (lane % 16) * ldaB + (lane / 16) * 16;
    uint32_t aAH = aH + aoff, aAL = aL + aoff;
    int brow = (lane & 7) + ((lane & 16) ? 8 : 0);
    uint32_t boff = (uint32_t)(colBase + brow) * 80 + ((lane & 8) ? 16 : 0);
    const int NC = K >> 5;
    {   // prologue: stage chunk 0
        uint4 t[2];
        loadB<NROWS>(t, WH, WL, K, 0, tid);
        storeB<NROWS>(bsPtr, t, tid);
    }
    __syncthreads();
    for (int c = 0; c < NC; ++c) {
        uint4 pre[2];
        bool hasNext = (c + 1) < NC;
        if (hasNext) loadB<NROWS>(pre, WH, WL, K, (c + 1) * 32, tid);
        uint32_t bufH = bsAddr + (c & 1) * BUFSZ + boff;
        uint32_t aCH = aAH + c * 64, aCL = aAL + c * 64;
        #pragma unroll
        for (int ks = 0; ks < 2; ++ks) {
            uint32_t ah_[MT][4], al_[MT][4];
            #pragma unroll
            for (int mt = 0; mt < MT; mt++) {
                ldm4(ah_[mt], aCH + mt * 16 * ldaB + ks * 32);
                ldm4(al_[mt], aCL + mt * 16 * ldaB + ks * 32);
            }
            #pragma unroll
            for (int q = 0; q < NTL / 2; q++) {
                uint32_t bh[4], bl[4];
                ldm4(bh, bufH + q * 16 * 80 + ks * 32);
                ldm4(bl, bufH + NROWS * 80 + q * 16 * 80 + ks * 32);
                #pragma unroll
                for (int mt = 0; mt < MT; mt++) {
                    mma_bf16(acc[mt][2 * q],     ah_[mt], bh[0], bh[1]);
                    mma_bf16(acc[mt][2 * q],     ah_[mt], bl[0], bl[1]);
                    mma_bf16(acc[mt][2 * q],     al_[mt], bh[0], bh[1]);
                    mma_bf16(acc[mt][2 * q + 1], ah_[mt], bh[2], bh[3]);
                    mma_bf16(acc[mt][2 * q + 1], ah_[mt], bl[2], bl[3]);
                    mma_bf16(acc[mt][2 * q + 1], al_[mt], bh[2], bh[3]);
                }
            }
        }
        if (hasNext) storeB<NROWS>(bsPtr + ((c + 1) & 1) * BUFSZ, pre, tid);
        __syncthreads();
    }
}

// ---------------- weight prep (fp32 -> bf16 hi/lo, gathers baked) ------------
__global__ void prep_kernel(const float* __restrict__ W1, const float* __restrict__ Wih,
                            const float* __restrict__ Whh, const float* __restrict__ Wx) {
    int i = blockIdx.x * 256 + threadIdx.x;
    if (i >= 147456) return;
    float v; __nv_bfloat16 *H, *L; int o;
    if (i < 40960) {
        int n = i / 320, k = i % 320;
        v = W1[n * 384 + (k < 192 ? k : k + 64)];
        H = W1h; L = W1l; o = i;
    } else if (i < 73728) {
        int j = i - 40960, n = j / 256, k = j % 256;
        v = (k < 128) ? Wih[n * 128 + k] : Whh[n * 128 + k - 128];
        H = Wrh; L = Wrl; o = j;
    } else if (i < 106496) {
        int j = i - 73728, n = j / 256, k = j % 256;
        v = (k < 128) ? Wih[(128 + n) * 128 + k] : Whh[(128 + n) * 128 + k - 128];
        H = Wzh; L = Wzl; o = j;
    } else if (i < 122880) {
        int j = i - 106496; v = Wih[256 * 128 + j]; H = Wnih; L = Wnil; o = j;
    } else if (i < 139264) {
        int j = i - 122880; v = Whh[256 * 128 + j]; H = Wnhh; L = Wnhl; o = j;
    } else {
        int j = i - 139264; v = Wx[j]; H = Wxh; L = Wxl; o = j;
    }
    __nv_bfloat16 h = __float2bfloat16(v);
    H[o] = h;
    L[o] = __float2bfloat16(v - __bfloat162float(h));
}

__global__ void u1_kernel(const float* __restrict__ u, const float* __restrict__ W1) {
    int b = blockIdx.x, n = threadIdx.x;
    float s = 0.f;
    #pragma unroll 8
    for (int k = 0; k < 64; k++)
        s += u[b * 64 + k] * W1[n * 384 + 192 + k];
    U1g[b * 128 + n] = s;
}

// ---------------- main fused kernel ------------------------------------------
__global__ __launch_bounds__(NTHR, 1)
void fused_kernel(const float* __restrict__ src, const float* __restrict__ dst,
                  const float* __restrict__ ea,  const float* __restrict__ hin,
                  const int*   __restrict__ batch, const float* __restrict__ winding,
                  const float* __restrict__ Ww,  const float* __restrict__ bw,
                  const float* __restrict__ gw,  const float* __restrict__ betaw,
                  const float* __restrict__ b1,  const float* __restrict__ g1,
                  const float* __restrict__ beta1,
                  const float* __restrict__ bih, const float* __restrict__ bhh,
                  const float* __restrict__ bx,
                  float* __restrict__ out_x, float* __restrict__ out_h, int E) {
    extern __shared__ char sm[];
    const uint32_t SP = sptr(sm);
    const int tid = threadIdx.x;
    const int lane = tid & 31, w = tid >> 5;
    const int wm = w & 3, wn = w >> 2;            // 4 x 4 warp grid
    const int rowBase = wm * 32, colBase = wn * 32;
    const int qr = lane >> 2, qc = (lane & 3) * 2;
    const int m0 = blockIdx.x * BM;
    float2* PART = reinterpret_cast<float2*>(sm + PART_OFF);
    int* bt_s = reinterpret_cast<int*>(sm + BT_OFF);
    char* bsPtr = sm + BS_OFF;
    const uint32_t bsAddr = SP + BS_OFF;

    // ---- Phase A: stage x-inputs (split to bf16 hi/lo) ----
    if (tid < BM) bt_s[tid] = (m0 + tid < E) ? batch[m0 + tid] : 0;
    #pragma unroll
    for (int t = 0; t < 3; t++) {
        const float* g = (t == 0) ? src : (t == 1) ? dst : ea;
        #pragma unroll
        for (int p = 0; p < 4; p++) {
            int idx = p * NTHR + tid;
            int r = idx >> 4, c4 = (idx & 15) * 4;
            float4 v = (m0 + r < E)
                ? *reinterpret_cast<const float4*>(g + (size_t)(m0 + r) * 64 + c4)
                : make_float4(0.f, 0.f, 0.f, 0.f);
            uint32_t h0, l0, h1, l1;
            split2(v.x, v.y, h0, l0); split2(v.z, v.w, h1, l1);
            int off = r * LDAX + (t * 64 + c4) * 2;
            *reinterpret_cast<uint2*>(sm + AXH_OFF + off) = make_uint2(h0, h1);
            *reinterpret_cast<uint2*>(sm + AXL_OFF + off) = make_uint2(l0, l1);
        }
    }
    // ---- winding MLP -> x cols [192,320) ----
    {
        int m = tid >> 2, q = tid & 3;
        float wa = 0.f, wb = 0.f;
        if (m0 + m < E) { wa = winding[(m0 + m) * 2]; wb = winding[(m0 + m) * 2 + 1]; }
        float v[32]; float s = 0.f, sq = 0.f;
        #pragma unroll
        for (int j = 0; j < 32; j++) {
            int c = q * 32 + j;
            v[j] = fmaf(wa, Ww[c * 2], fmaf(wb, Ww[c * 2 + 1], bw[c]));
            s += v[j]; sq += v[j] * v[j];
        }
        s  += __shfl_xor_sync(0xffffffffu, s, 1);  s  += __shfl_xor_sync(0xffffffffu, s, 2);
        sq += __shfl_xor_sync(0xffffffffu, sq, 1); sq += __shfl_xor_sync(0xffffffffu, sq, 2);
        float mu = s * (1.f / 128.f);
        float inv = rsqrtf(sq * (1.f / 128.f) - mu * mu + LN_EPS);
        #pragma unroll
        for (int j = 0; j < 32; j += 2) {
            int c = q * 32 + j;
            float o0 = fmaxf(fmaf((v[j] - mu) * inv, gw[c], betaw[c]), 0.f);
            float o1 = fmaxf(fmaf((v[j + 1] - mu) * inv, gw[c + 1], betaw[c + 1]), 0.f);
            uint32_t H, L; split2(o0, o1, H, L);
            int off = m * LDAX + (192 + c) * 2;
            *reinterpret_cast<uint32_t*>(sm + AXH_OFF + off) = H;
            *reinterpret_cast<uint32_t*>(sm + AXL_OFF + off) = L;
        }
    }
    __syncthreads();

    int c8[8];
    #pragma unroll
    for (int j = 0; j < 8; j++) c8[j] = colBase + (j >> 1) * 8 + qc + (j & 1);

    // ---- GEMM1: x(320) @ W1^T -> +U1+b1 -> LN -> relu -> cat[:,0:128] ----
    {
        float acc[2][4][4] = {};
        run_gemm<2, 4, 128>(acc, SP + AXH_OFF + rowBase * LDAX,
                            SP + AXL_OFF + rowBase * LDAX, LDAX,
                            W1h, W1l, 320, bsPtr, bsAddr, colBase, tid);
        // stage h -> cat cols [128,256)  (x region is dead now except where cat lives)
        #pragma unroll
        for (int p = 0; p < 8; p++) {
            int idx = p * NTHR + tid;
            int r = idx >> 5, c4 = (idx & 31) * 4;
            float4 v = (m0 + r < E)
                ? *reinterpret_cast<const float4*>(hin + (size_t)(m0 + r) * 128 + c4)
                : make_float4(0.f, 0.f, 0.f, 0.f);
            uint32_t h0, l0, h1, l1;
            split2(v.x, v.y, h0, l0); split2(v.z, v.w, h1, l1);
            int off = r * LDAC + (128 + c4) * 2;
            *reinterpret_cast<uint2*>(sm + ACH_OFF + off) = make_uint2(h0, h1);
            *reinterpret_cast<uint2*>(sm + ACL_OFF + off) = make_uint2(l0, l1);
        }
        float b1v[8], g1v[8], be1[8];
        #pragma unroll
        for (int j = 0; j < 8; j++) { b1v[j] = b1[c8[j]]; g1v[j] = g1[c8[j]]; be1[j] = beta1[c8[j]]; }
        #pragma unroll
        for (int mt = 0; mt < 2; mt++)
            #pragma unroll
            for (int h = 0; h < 2; h++) {
                int row = rowBase + mt * 16 + qr + h * 8;
                const float* u1r = U1g + bt_s[row] * 128;
                float s = 0.f, sq = 0.f;
                #pragma unroll
                for (int j = 0; j < 8; j++) {
                    float vv = acc[mt][j >> 1][2 * h + (j & 1)] + b1v[j] + u1r[c8[j]];
                    acc[mt][j >> 1][2 * h + (j & 1)] = vv;
                    s += vv; sq += vv * vv;
                }
                s  += __shfl_xor_sync(0xffffffffu, s, 1);  s  += __shfl_xor_sync(0xffffffffu, s, 2);
                sq += __shfl_xor_sync(0xffffffffu, sq, 1); sq += __shfl_xor_sync(0xffffffffu, sq, 2);
                if ((lane & 3) == 0) PART[row * 4 + wn] = make_float2(s, sq);
            }
        __syncthreads();
        #pragma unroll
        for (int mt = 0; mt < 2; mt++)
            #pragma unroll
            for (int h = 0; h < 2; h++) {
                int row = rowBase + mt * 16 + qr + h * 8;
                float2 p0 = PART[row * 4], p1 = PART[row * 4 + 1],
                       p2 = PART[row * 4 + 2], p3 = PART[row * 4 + 3];
                float S = p0.x + p1.x + p2.x + p3.x;
                float Q = p0.y + p1.y + p2.y + p3.y;
                float mu = S * (1.f / 128.f);
                float inv = rsqrtf(Q * (1.f / 128.f) - mu * mu + LN_EPS);
                #pragma unroll
                for (int nt = 0; nt < 4; nt++) {
                    float o0 = fmaxf(fmaf((acc[mt][nt][2 * h] - mu) * inv,
                                          g1v[nt * 2], be1[nt * 2]), 0.f);
                    float o1 = fmaxf(fmaf((acc[mt][nt][2 * h + 1] - mu) * inv,
                                          g1v[nt * 2 + 1], be1[nt * 2 + 1]), 0.f);
                    uint32_t H, L; split2(o0, o1, H, L);
                    int off = row * LDAC + c8[nt * 2] * 2;
                    *reinterpret_cast<uint32_t*>(sm + ACH_OFF + off) = H;
                    *reinterpret_cast<uint32_t*>(sm + ACL_OFF + off) = L;
                }
            }
    }
    // (run_gemm prologue sync publishes cat writes before A reads)

    // ---- GRU, sequential gates: r -> rH -> n -> z/blend ----
    const uint32_t aCH = SP + ACH_OFF + rowBase * LDAC;
    const uint32_t aCL = SP + ACL_OFF + rowBase * LDAC;
    float keep[2][4][4];     // r, then r*(h_n+bh_n), then n
    {
        float acc[2][4][4] = {};
        run_gemm<2, 4, 128>(acc, aCH, aCL, LDAC, Wrh, Wrl, 256, bsPtr, bsAddr, colBase, tid);
        #pragma unroll
        for (int mt = 0; mt < 2; mt++)
            #pragma unroll
            for (int j = 0; j < 8; j++) {
                float br = bih[c8[j]] + bhh[c8[j]];
                int nt = j >> 1, e = j & 1;
                #pragma unroll
                for (int h = 0; h < 2; h++)
                    keep[mt][nt][2 * h + e] = sigf(acc[mt][nt][2 * h + e] + br);
            }
    }
    {
        float acc[2][4][4] = {};
        run_gemm<2, 4, 128>(acc, aCH + 256, aCL + 256, LDAC, Wnhh, Wnhl, 128,
                            bsPtr, bsAddr, colBase, tid);
        #pragma unroll
        for (int mt = 0; mt < 2; mt++)
            #pragma unroll
            for (int j = 0; j < 8; j++) {
                float bn = bhh[256 + c8[j]];
                int nt = j >> 1, e = j & 1;
                #pragma unroll
                for (int h = 0; h < 2; h++)
                    keep[mt][nt][2 * h + e] *= (acc[mt][nt][2 * h + e] + bn);
            }
    }
    {
        float acc[2][4][4] = {};
        run_gemm<2, 4, 128>(acc, aCH, aCL, LDAC, Wnih, Wnil, 128,
                            bsPtr, bsAddr, colBase, tid);
        #pragma unroll
        for (int mt = 0; mt < 2; mt++)
            #pragma unroll
            for (int j = 0; j < 8; j++) {
                float bn = bih[256 + c8[j]];
                int nt = j >> 1, e = j & 1;
                #pragma unroll
                for (int h = 0; h < 2; h++)
                    keep[mt][nt][2 * h + e] =
                        tanhfast(acc[mt][nt][2 * h + e] + bn + keep[mt][nt][2 * h + e]);
            }
    }
    {
        float acc[2][4][4] = {};
        run_gemm<2, 4, 128>(acc, aCH, aCL, LDAC, Wzh, Wzl, 256, bsPtr, bsAddr, colBase, tid);
        #pragma unroll
        for (int mt = 0; mt < 2; mt++)
            #pragma unroll
            for (int h = 0; h < 2; h++) {
                int row = rowBase + mt * 16 + qr + h * 8;
                #pragma unroll
                for (int nt = 0; nt < 4; nt++) {
                    int c0 = c8[nt * 2];
                    uint32_t Hh = *reinterpret_cast<uint32_t*>(sm + ACH_OFF + row * LDAC + (128 + c0) * 2);
                    uint32_t Hl = *reinterpret_cast<uint32_t*>(sm + ACL_OFF + row * LDAC + (128 + c0) * 2);
                    __nv_bfloat162 bh2 = *reinterpret_cast<__nv_bfloat162*>(&Hh);
                    __nv_bfloat162 bl2 = *reinterpret_cast<__nv_bfloat162*>(&Hl);
                    float hp0 = __bfloat162float(bh2.x) + __bfloat162float(bl2.x);
                    float hp1 = __bfloat162float(bh2.y) + __bfloat162float(bl2.y);
                    float z0 = sigf(acc[mt][nt][2 * h] + bih[128 + c0] + bhh[128 + c0]);
                    float z1 = sigf(acc[mt][nt][2 * h + 1] + bih[128 + c0 + 1] + bhh[128 + c0 + 1]);
                    float n0 = keep[mt][nt][2 * h], n1 = keep[mt][nt][2 * h + 1];
                    float hn0 = fmaf(z0, hp0 - n0, n0);
                    float hn1 = fmaf(z1, hp1 - n1, n1);
                    if (m0 + row < E)
                        *reinterpret_cast<float2*>(out_h + (size_t)(m0 + row) * 128 + c0) =
                            make_float2(hn0, hn1);
                    // h_new -> cat cols [0,128) (x1 region, dead now)
                    uint32_t H, L; split2(hn0, hn1, H, L);
                    *reinterpret_cast<uint32_t*>(sm + ACH_OFF + row * LDAC + c0 * 2) = H;
                    *reinterpret_cast<uint32_t*>(sm + ACL_OFF + row * LDAC + c0 * 2) = L;
                }
            }
    }
    // ---- x_out = h_new @ Wx^T + bx  (warp grid 8 x 2) ----
    {
        const int rb2 = (w & 7) * 16, cb2 = (w >> 3) * 32;
        float accX[1][4][4] = {};
        run_gemm<1, 4, 64>(accX, SP + ACH_OFF + rb2 * LDAC,
                           SP + ACL_OFF + rb2 * LDAC, LDAC,
                           Wxh, Wxl, 128, bsPtr, bsAddr, cb2, tid);
        #pragma unroll
        for (int h = 0; h < 2; h++) {
            int row = rb2 + qr + h * 8;
            if (m0 + row < E) {
                #pragma unroll
                for (int nt = 0; nt < 4; nt++) {
                    int c = cb2 + nt * 8 + qc;
                    *reinterpret_cast<float2*>(out_x + (size_t)(m0 + row) * 64 + c) =
                        make_float2(accX[0][nt][2 * h] + bx[c],
                                    accX[0][nt][2 * h + 1] + bx[c + 1]);
                }
            }
        }
    }
}

// ---------------------------------------------------------------------------
extern "C" void kernel_launch(void* const* d_in, const int* in_sizes, int n_in,
                              void* d_out, int out_size) {
    const float* src     = (const float*)d_in[0];
    const float* dst     = (const float*)d_in[1];
    const float* ea      = (const float*)d_in[2];
    const float* hin     = (const float*)d_in[3];
    const float* u       = (const float*)d_in[4];
    const int*   batch   = (const int*)  d_in[5];
    const float* winding = (const float*)d_in[6];
    const float* Ww      = (const float*)d_in[7];
    const float* bw      = (const float*)d_in[8];
    const float* gw      = (const float*)d_in[9];
    const float* betaw   = (const float*)d_in[10];
    const float* W1      = (const float*)d_in[11];
    const float* b1      = (const float*)d_in[12];
    const float* g1      = (const float*)d_in[13];
    const float* beta1   = (const float*)d_in[14];
    const float* Wih     = (const float*)d_in[15];
    const float* Whh     = (const float*)d_in[16];
    const float* bih     = (const float*)d_in[17];
    const float* bhh     = (const float*)d_in[18];
    const float* Wx      = (const float*)d_in[19];
    const float* bx      = (const float*)d_in[20];

    int E = in_sizes[0] / 64;
    int B = in_sizes[4] / 64;
    float* out_x = (float*)d_out;
    float* out_h = (float*)d_out + (size_t)E * 64;

    cudaFuncSetAttribute(fused_kernel,
                         cudaFuncAttributeMaxDynamicSharedMemorySize, SMEM_BYTES);
    prep_kernel<<<576, 256>>>(W1, Wih, Whh, Wx);
    u1_kernel<<<B, 128>>>(u, W1);
    int grid = (E + BM - 1) / BM;
    fused_kernel<<<grid, NTHR, SMEM_BYTES>>>(src, dst, ea, hin, batch, winding,
                                             Ww, bw, gw, betaw,
                                             b1, g1, beta1, bih, bhh, bx,
                                             out_x, out_h, E);
}